// round 11
// baseline (speedup 1.0000x reference)
#include <cuda_runtime.h>
#include <cuda_fp16.h>
#include <cstdint>

// ================================================================
// AutoGNN, 7 launches — persistent fp16 GEMMs, W resident in smem:
//   1) split_w:  W1/W2/WL -> fp16 hi/lo (WL padded 40->64 rows)
//   2) x16:      X -> fp16
//   3) gemm_p:   Y = X16 @ W1^T    [152 CTAs, W loaded once,
//   4) gather:   H = fp16(relu(mean(Y[nbrs])))    A cp.async 2-buf]
//   5) gemm_p:   Y = H @ W2^T
//   6) gather
//   7) gemm_p<64,40>: out = H @ WL^T (fp32)
// GEMM: mma.sync m16n8k16 fp16, 2-term W split (err 2^-21), fp32 acc.
// CTA tile 256 x NOUT, 16 warps (warp tile 32 x NOUT/2).
// ================================================================

#define FEAT 128
#define SAMPLE 25
#define CLASSES 40
#define MAXN 100000
#define RS 272   // smem row stride bytes: conflict-free ldmatrix
#define NCTAS 152

__device__ __half g_Y[(size_t)MAXN * FEAT];
__device__ __half g_H[(size_t)MAXN * FEAT];
__device__ __half g_X16[(size_t)MAXN * FEAT];
__device__ __half g_W1hi[128 * 128], g_W1lo[128 * 128];
__device__ __half g_W2hi[128 * 128], g_W2lo[128 * 128];
__device__ __half g_WLhi[64 * 128],  g_WLlo[64 * 128];

__device__ __forceinline__ uint32_t smem_u32(const void* p) {
    uint32_t a;
    asm("{ .reg .u64 t; cvta.to.shared.u64 t, %1; cvt.u32.u64 %0, t; }" : "=r"(a) : "l"(p));
    return a;
}
__device__ __forceinline__ void ldsm4(uint32_t addr, uint32_t& r0, uint32_t& r1,
                                      uint32_t& r2, uint32_t& r3) {
    asm volatile("ldmatrix.sync.aligned.m8n8.x4.shared.b16 {%0,%1,%2,%3}, [%4];"
                 : "=r"(r0), "=r"(r1), "=r"(r2), "=r"(r3) : "r"(addr));
}
__device__ __forceinline__ void mma_f16(float* c, const uint32_t* a,
                                        uint32_t b0, uint32_t b1) {
    asm volatile(
        "mma.sync.aligned.m16n8k16.row.col.f32.f16.f16.f32 "
        "{%0,%1,%2,%3}, {%4,%5,%6,%7}, {%8,%9}, {%0,%1,%2,%3};"
        : "+f"(c[0]), "+f"(c[1]), "+f"(c[2]), "+f"(c[3])
        : "r"(a[0]), "r"(a[1]), "r"(a[2]), "r"(a[3]), "r"(b0), "r"(b1));
}
__device__ __forceinline__ void cp_async16(uint32_t saddr, const void* gaddr,
                                           uint32_t src_sz) {
    asm volatile("cp.async.cg.shared.global [%0], [%1], 16, %2;"
                 :: "r"(saddr), "l"(gaddr), "r"(src_sz));
}
#define CP_COMMIT() asm volatile("cp.async.commit_group;" ::: "memory")
#define CP_WAIT1()  asm volatile("cp.async.wait_group 1;" ::: "memory")

// ================================================================
// Persistent GEMM: C[t*256.., CST] = A @ (Wh + Wl)^T
// smem: [Wh NOUT*RS][Wl NOUT*RS][Abuf0 256*RS][Abuf1 256*RS]
// 512 threads / 16 warps; warp (wm,wn) = (wid>>1, wid&1).
// ================================================================
template<int NOUT, int CST, typename TOUT>
__global__ __launch_bounds__(512, 1) void gemm_pers_kernel(
    const __half* __restrict__ A,
    const __half* __restrict__ Wh, const __half* __restrict__ Wl,
    TOUT* __restrict__ C, int n)
{
    extern __shared__ char smem[];
    constexpr int OFF_WL = NOUT * RS;
    constexpr int OFF_A0 = 2 * NOUT * RS;
    constexpr int ABUF   = 256 * RS;
    constexpr int WN = NOUT / 2;       // warp n-extent (64 or 32)
    constexpr int NT = WN / 8;         // n8 tiles per warp (8 or 4)

    const int tid  = threadIdx.x;
    const int wid  = tid >> 5;
    const int lane = tid & 31;
    const int wm   = wid >> 1;         // 0..7 -> m = wm*32
    const int wn   = wid & 1;          // 0..1 -> n = wn*WN
    const uint32_t sb = smem_u32(smem);

    // ---- W resident load (once per CTA) ----
    #pragma unroll
    for (int i = 0; i < NOUT / 32; i++) {
        int t = i * 512 + tid;
        int row = t >> 4;
        int c16 = t & 15;
        size_t g = (size_t)row * 128 + c16 * 8;
        int off = row * RS + c16 * 16;
        *reinterpret_cast<uint4*>(smem + off) =
            *reinterpret_cast<const uint4*>(Wh + g);
        *reinterpret_cast<uint4*>(smem + OFF_WL + off) =
            *reinterpret_cast<const uint4*>(Wl + g);
    }

    const int tiles  = (n + 255) >> 8;
    const int stride = gridDim.x;

    // ---- A tile prefetch: 256 rows x 256 B, zfill OOB rows ----
    auto prefetch = [&](int t, int buf) {
        const uint32_t abase = sb + OFF_A0 + buf * ABUF;
        const int m0 = t << 8;
        #pragma unroll
        for (int i = 0; i < 8; i++) {
            int k = i * 512 + tid;         // 4096: row 0..255, c16 0..15
            int row = k >> 4;
            int c16 = k & 15;
            int grow = m0 + row;
            uint32_t sz = (grow < n) ? 16u : 0u;
            int gc = (grow < n) ? grow : 0;
            size_t g = (size_t)gc * 128 + c16 * 8;
            cp_async16(abase + (uint32_t)(row * RS + c16 * 16), A + g, sz);
        }
    };

    // lane-derived ldmatrix offsets
    const int l15   = lane & 15;
    const int aHalf = (lane & 16) ? 16 : 0;
    const uint32_t aRowOff0 = (uint32_t)((wm * 32 + l15) * RS + aHalf);
    const uint32_t aRowOff1 = aRowOff0 + 16 * RS;
    const int bRow  = (lane & 7) + ((lane & 16) ? 8 : 0);
    const int bHalf = (lane & 8) ? 16 : 0;
    uint32_t bRowByte[NT / 2];
    #pragma unroll
    for (int jp = 0; jp < NT / 2; jp++)
        bRowByte[jp] = (uint32_t)((wn * WN + jp * 16 + bRow) * RS + bHalf);

    int t0 = blockIdx.x;
    if (t0 < tiles) prefetch(t0, 0);
    CP_COMMIT();

    int it = 0;
    for (int t = t0; t < tiles; t += stride, it++) {
        const int buf = it & 1;
        int tn = t + stride;
        if (tn < tiles) prefetch(tn, buf ^ 1);
        CP_COMMIT();
        CP_WAIT1();
        __syncthreads();

        const uint32_t aB  = sb + OFF_A0 + buf * ABUF;
        const uint32_t whB = sb;
        const uint32_t wlB = sb + OFF_WL;

        float c[2][NT][4];
        #pragma unroll
        for (int mt = 0; mt < 2; mt++)
            #pragma unroll
            for (int j = 0; j < NT; j++)
                #pragma unroll
                for (int q = 0; q < 4; q++) c[mt][j][q] = 0.f;

        #pragma unroll
        for (int ks = 0; ks < 8; ks++) {
            const uint32_t kb = ks * 32;
            uint32_t a[2][4];
            ldsm4(aB + aRowOff0 + kb, a[0][0], a[0][1], a[0][2], a[0][3]);
            ldsm4(aB + aRowOff1 + kb, a[1][0], a[1][1], a[1][2], a[1][3]);
            uint32_t bh[NT][2], bl[NT][2];
            #pragma unroll
            for (int jp = 0; jp < NT / 2; jp++) {
                ldsm4(whB + bRowByte[jp] + kb,
                      bh[2 * jp][0], bh[2 * jp][1], bh[2 * jp + 1][0], bh[2 * jp + 1][1]);
                ldsm4(wlB + bRowByte[jp] + kb,
                      bl[2 * jp][0], bl[2 * jp][1], bl[2 * jp + 1][0], bl[2 * jp + 1][1]);
            }
            #pragma unroll
            for (int mt = 0; mt < 2; mt++)
                #pragma unroll
                for (int j = 0; j < NT; j++) {
                    mma_f16(c[mt][j], a[mt], bh[j][0], bh[j][1]);
                    mma_f16(c[mt][j], a[mt], bl[j][0], bl[j][1]);
                }
        }

        // ---- epilogue ----
        const int m0 = t << 8;
        const int qrow = lane >> 2;
        const int qcol = (lane & 3) * 2;
        #pragma unroll
        for (int mt = 0; mt < 2; mt++) {
            #pragma unroll
            for (int half = 0; half < 2; half++) {
                int m_g = m0 + wm * 32 + mt * 16 + qrow + half * 8;
                if (m_g < n) {
                    TOUT* crow = C + (size_t)m_g * CST;
                    #pragma unroll
                    for (int j = 0; j < NT; j++) {
                        int n_g = wn * WN + j * 8 + qcol;
                        if (CST == 128 || n_g < CST) {
                            float v0 = c[mt][j][half * 2];
                            float v1 = c[mt][j][half * 2 + 1];
                            if constexpr (sizeof(TOUT) == 2) {
                                __half2 hv = __floats2half2_rn(v0, v1);
                                *reinterpret_cast<__half2*>(crow + n_g) = hv;
                            } else {
                                *reinterpret_cast<float2*>(crow + n_g) =
                                    make_float2(v0, v1);
                            }
                        }
                    }
                }
            }
        }
        __syncthreads();   // buf fully consumed before next iter refills it
    }
}

// ---------------- gather: fp16 Y -> fp16 H ----------------------------------
__global__ __launch_bounds__(256) void gather_h16_kernel(
    const __half* __restrict__ Y, const int* __restrict__ nbrs,
    __half* __restrict__ H, int n)
{
    const int warp = (blockIdx.x * blockDim.x + threadIdx.x) >> 5;
    const int lane = threadIdx.x & 31;
    if (warp >= n) return;

    int idx = 0;
    if (lane < SAMPLE) idx = nbrs[(size_t)warp * SAMPLE + lane];

    float acc[4] = { 0.f, 0.f, 0.f, 0.f };
    #pragma unroll
    for (int j = 0; j < SAMPLE; j++) {
        int row = __shfl_sync(0xffffffffu, idx, j);
        uint2 u = __ldg(reinterpret_cast<const uint2*>(Y + (size_t)row * 128) + lane);
        __half2 p0 = *reinterpret_cast<__half2*>(&u.x);
        __half2 p1 = *reinterpret_cast<__half2*>(&u.y);
        float2 f0 = __half22float2(p0);
        float2 f1 = __half22float2(p1);
        acc[0] += f0.x; acc[1] += f0.y; acc[2] += f1.x; acc[3] += f1.y;
    }
    const float s = 1.0f / (float)SAMPLE;
    __half h[4] = { __float2half(fmaxf(acc[0] * s, 0.f)),
                    __float2half(fmaxf(acc[1] * s, 0.f)),
                    __float2half(fmaxf(acc[2] * s, 0.f)),
                    __float2half(fmaxf(acc[3] * s, 0.f)) };
    *(reinterpret_cast<uint2*>(H + (size_t)warp * 128) + lane) =
        *reinterpret_cast<uint2*>(h);
}

// ---------------- X -> fp16 --------------------------------------------------
__global__ void x16_kernel(const float* __restrict__ X,
                           __half* __restrict__ X16, int total4)
{
    int i = blockIdx.x * blockDim.x + threadIdx.x;
    if (i >= total4) return;
    float4 v = __ldg(reinterpret_cast<const float4*>(X) + i);
    __half h[4] = { __float2half(v.x), __float2half(v.y),
                    __float2half(v.z), __float2half(v.w) };
    *(reinterpret_cast<uint2*>(X16) + i) = *reinterpret_cast<uint2*>(h);
}

// ---------------- weight splitter (fp16 hi/lo) -------------------------------
__global__ void split_w_kernel(const float* __restrict__ W1,
                               const float* __restrict__ W2,
                               const float* __restrict__ WL,
                               __half* w1h, __half* w1l,
                               __half* w2h, __half* w2l,
                               __half* wlh, __half* wll)
{
    int i = blockIdx.x * blockDim.x + threadIdx.x;  // 0 .. 40959
    float v; __half *ph, *pl; int idx;
    if (i < 16384)      { v = W1[i];            ph = w1h; pl = w1l; idx = i; }
    else if (i < 32768) { idx = i - 16384; v = W2[idx]; ph = w2h; pl = w2l; }
    else if (i < 40960) {
        idx = i - 32768;                 // padded [64][128]
        int row = idx >> 7;
        v = (row < CLASSES) ? WL[idx] : 0.f;
        ph = wlh; pl = wll;
    } else return;
    __half h = __float2half(v);
    ph[idx] = h;
    pl[idx] = __float2half(v - __half2float(h));
}

// ================================================================
extern "C" void kernel_launch(void* const* d_in, const int* in_sizes, int n_in,
                              void* d_out, int out_size)
{
    const float* X    = (const float*)d_in[0];
    const int*   nbrs = (const int*)  d_in[1];
    const float* W1   = (const float*)d_in[2];
    const float* W2   = (const float*)d_in[3];
    const float* WL   = (const float*)d_in[4];
    float*       out  = (float*)d_out;
    const int n = in_sizes[1] / SAMPLE;

    __half *Y, *H, *X16, *w1h, *w1l, *w2h, *w2l, *wlh, *wll;
    cudaGetSymbolAddress((void**)&Y,   g_Y);
    cudaGetSymbolAddress((void**)&H,   g_H);
    cudaGetSymbolAddress((void**)&X16, g_X16);
    cudaGetSymbolAddress((void**)&w1h, g_W1hi);
    cudaGetSymbolAddress((void**)&w1l, g_W1lo);
    cudaGetSymbolAddress((void**)&w2h, g_W2hi);
    cudaGetSymbolAddress((void**)&w2l, g_W2lo);
    cudaGetSymbolAddress((void**)&wlh, g_WLhi);
    cudaGetSymbolAddress((void**)&wll, g_WLlo);

    // smem: W (2*NOUT*RS) + 2 A buffers (256*RS each)
    const int SM128 = RS * (2 * 128) + 2 * RS * 256;  // 208896
    const int SM64  = RS * (2 * 64)  + 2 * RS * 256;  // 174080
    cudaFuncSetAttribute(gemm_pers_kernel<128, 128, __half>,
                         cudaFuncAttributeMaxDynamicSharedMemorySize, SM128);
    cudaFuncSetAttribute(gemm_pers_kernel<64, 40, float>,
                         cudaFuncAttributeMaxDynamicSharedMemorySize, SM64);

    const int sg = (n * 32 + 255) / 256;
    const int ag = (n + 7) / 8;

    split_w_kernel<<<160, 256>>>(W1, W2, WL, w1h, w1l, w2h, w2l, wlh, wll);
    x16_kernel<<<sg, 256>>>(X, X16, n * 32);
    gemm_pers_kernel<128, 128, __half><<<NCTAS, 512, SM128>>>(X16, w1h, w1l, Y, n);
    gather_h16_kernel<<<ag, 256>>>(Y, nbrs, H, n);
    gemm_pers_kernel<128, 128, __half><<<NCTAS, 512, SM128>>>(H, w2h, w2l, Y, n);
    gather_h16_kernel<<<ag, 256>>>(Y, nbrs, H, n);
    gemm_pers_kernel<64, 40, float><<<NCTAS, 512, SM64>>>(H, wlh, wll, out, n);
}